// round 1
// baseline (speedup 1.0000x reference)
#include <cuda_runtime.h>
#include <math.h>

#define BB 4
#define NN_SEQ 4096
#define DD 768

// Scratch (allocation-free rule: __device__ globals)
__device__ float g_qkv[(size_t)BB * NN_SEQ * (3 * DD)];       // 151 MB
__device__ float g_scores[(size_t)BB * NN_SEQ * NN_SEQ];      // 268 MB
__device__ float g_ctx[(size_t)BB * NN_SEQ * DD];             // 50 MB

// ---------------------------------------------------------------------------
// Generic fp32 SGEMM: C = alpha * A * op(B) + bias
//   A: [M,K] row-major, lda
//   B: NN -> [K,N] row-major, ldb ; NT -> [N,K] row-major, ldb (op(B)=B^T)
//   C: [M,N] row-major, ldc
// BM=BN=128, BK=16, 256 threads, 8x8 per thread. All dims assumed tile-exact.
// ---------------------------------------------------------------------------
template <bool TRANSB, bool HAS_BIAS>
__global__ __launch_bounds__(256) void sgemm_kernel(
    const float* __restrict__ A, const float* __restrict__ B,
    const float* __restrict__ bias, float* __restrict__ C,
    int K, int lda, int ldb, int ldc, float alpha,
    long long strideA, long long strideB, long long strideC)
{
    constexpr int BM = 128, BN = 128, BK = 16;
    __shared__ float As[BK][BM];
    __shared__ float Bs[BK][BN];

    const int t  = threadIdx.x;          // 0..255
    const int bx = blockIdx.x;           // N tile
    const int by = blockIdx.y;           // M tile
    const int bz = blockIdx.z;           // batch

    A += (size_t)bz * strideA;
    B += (size_t)bz * strideB;
    C += (size_t)bz * strideC;

    const int tx = t & 15;               // 0..15  -> N
    const int ty = t >> 4;               // 0..15  -> M

    float acc[8][8];
#pragma unroll
    for (int i = 0; i < 8; i++)
#pragma unroll
        for (int j = 0; j < 8; j++) acc[i][j] = 0.0f;

    for (int k0 = 0; k0 < K; k0 += BK) {
        // --- load A tile (transposed store: As[k][m]) ---
#pragma unroll
        for (int s = 0; s < 2; s++) {
            int f   = t + s * 256;       // 0..511 float4 slots
            int row = f >> 2;            // 0..127
            int kq  = (f & 3) * 4;       // 0,4,8,12
            float4 v = *(const float4*)(A + (size_t)(by * BM + row) * lda + k0 + kq);
            As[kq + 0][row] = v.x;
            As[kq + 1][row] = v.y;
            As[kq + 2][row] = v.z;
            As[kq + 3][row] = v.w;
        }
        // --- load B tile ---
        if (TRANSB) {
#pragma unroll
            for (int s = 0; s < 2; s++) {
                int f  = t + s * 256;
                int n  = f >> 2;         // 0..127
                int kq = (f & 3) * 4;
                float4 v = *(const float4*)(B + (size_t)(bx * BN + n) * ldb + k0 + kq);
                Bs[kq + 0][n] = v.x;
                Bs[kq + 1][n] = v.y;
                Bs[kq + 2][n] = v.z;
                Bs[kq + 3][n] = v.w;
            }
        } else {
#pragma unroll
            for (int s = 0; s < 2; s++) {
                int f  = t + s * 256;
                int kr = f >> 5;         // 0..15
                int c4 = (f & 31) * 4;   // 0..124
                float4 v = *(const float4*)(B + (size_t)(k0 + kr) * ldb + bx * BN + c4);
                *(float4*)&Bs[kr][c4] = v;
            }
        }
        __syncthreads();

#pragma unroll
        for (int kk = 0; kk < BK; kk++) {
            float ra[8], rb[8];
#pragma unroll
            for (int i = 0; i < 8; i++) ra[i] = As[kk][ty * 8 + i];
#pragma unroll
            for (int j = 0; j < 8; j++) rb[j] = Bs[kk][tx * 8 + j];
#pragma unroll
            for (int i = 0; i < 8; i++)
#pragma unroll
                for (int j = 0; j < 8; j++) acc[i][j] = fmaf(ra[i], rb[j], acc[i][j]);
        }
        __syncthreads();
    }

    // --- epilogue ---
    float bcol[8];
#pragma unroll
    for (int j = 0; j < 8; j++)
        bcol[j] = HAS_BIAS ? bias[bx * BN + tx * 8 + j] : 0.0f;

#pragma unroll
    for (int i = 0; i < 8; i++) {
        size_t row = (size_t)(by * BM + ty * 8 + i);
        float* cp = C + row * ldc + bx * BN + tx * 8;
#pragma unroll
        for (int j4 = 0; j4 < 8; j4 += 4) {
            float4 v;
            v.x = acc[i][j4 + 0] * alpha + bcol[j4 + 0];
            v.y = acc[i][j4 + 1] * alpha + bcol[j4 + 1];
            v.z = acc[i][j4 + 2] * alpha + bcol[j4 + 2];
            v.w = acc[i][j4 + 3] * alpha + bcol[j4 + 3];
            *(float4*)(cp + j4) = v;
        }
    }
}

// ---------------------------------------------------------------------------
// Row softmax over 4096 columns. One block (256 thr) per row, float4 I/O.
// ---------------------------------------------------------------------------
__global__ __launch_bounds__(256) void softmax_kernel(float* __restrict__ scores)
{
    const int ncols4 = NN_SEQ / 4;   // 1024 float4
    float4* row = (float4*)(scores + (size_t)blockIdx.x * NN_SEQ);
    const int t = threadIdx.x;

    __shared__ float red[8];

    // pass 1: max
    float m = -1e30f;
    for (int i = t; i < ncols4; i += 256) {
        float4 v = row[i];
        m = fmaxf(m, fmaxf(fmaxf(v.x, v.y), fmaxf(v.z, v.w)));
    }
#pragma unroll
    for (int o = 16; o > 0; o >>= 1) m = fmaxf(m, __shfl_xor_sync(0xffffffffu, m, o));
    if ((t & 31) == 0) red[t >> 5] = m;
    __syncthreads();
    if (t < 8) {
        float v = red[t];
#pragma unroll
        for (int o = 4; o > 0; o >>= 1) v = fmaxf(v, __shfl_xor_sync(0xffu, v, o));
        if (t == 0) red[0] = v;
    }
    __syncthreads();
    m = red[0];
    __syncthreads();

    // pass 2: exp + sum
    float s = 0.0f;
    for (int i = t; i < ncols4; i += 256) {
        float4 v = row[i];
        v.x = __expf(v.x - m); v.y = __expf(v.y - m);
        v.z = __expf(v.z - m); v.w = __expf(v.w - m);
        s += v.x + v.y + v.z + v.w;
        row[i] = v;
    }
#pragma unroll
    for (int o = 16; o > 0; o >>= 1) s += __shfl_xor_sync(0xffffffffu, s, o);
    if ((t & 31) == 0) red[t >> 5] = s;
    __syncthreads();
    if (t < 8) {
        float v = red[t];
#pragma unroll
        for (int o = 4; o > 0; o >>= 1) v += __shfl_xor_sync(0xffu, v, o);
        if (t == 0) red[0] = v;
    }
    __syncthreads();
    float inv = 1.0f / red[0];

    // pass 3: normalize
    for (int i = t; i < ncols4; i += 256) {
        float4 v = row[i];
        v.x *= inv; v.y *= inv; v.z *= inv; v.w *= inv;
        row[i] = v;
    }
}

// ---------------------------------------------------------------------------
extern "C" void kernel_launch(void* const* d_in, const int* in_sizes, int n_in,
                              void* d_out, int out_size)
{
    const float* x     = (const float*)d_in[0];   // [4,4096,768]
    const float* w_qkv = (const float*)d_in[1];   // [768,2304]
    const float* b_qkv = (const float*)d_in[2];   // [2304]
    const float* w_out = (const float*)d_in[3];   // [768,768]
    const float* b_out = (const float*)d_in[4];   // [768]
    float* out = (float*)d_out;                   // [4,4096,768]

    float *qkv, *scores, *ctx;
    cudaGetSymbolAddress((void**)&qkv,    g_qkv);
    cudaGetSymbolAddress((void**)&scores, g_scores);
    cudaGetSymbolAddress((void**)&ctx,    g_ctx);

    const float SCALE = 1.0f / sqrtf((float)DD);
    dim3 blk(256);

    // 1) QKV projection: [16384,768] x [768,2304] + b  -> qkv
    sgemm_kernel<false, true><<<dim3(3 * DD / 128, BB * NN_SEQ / 128, 1), blk>>>(
        x, w_qkv, b_qkv, qkv,
        DD, DD, 3 * DD, 3 * DD, 1.0f, 0, 0, 0);

    // 2) scores = SCALE * Q @ K^T  (per batch, NT)
    sgemm_kernel<true, false><<<dim3(NN_SEQ / 128, NN_SEQ / 128, BB), blk>>>(
        qkv /*Q cols 0..767*/, qkv + DD /*K cols 768..1535*/, nullptr, scores,
        DD, 3 * DD, 3 * DD, NN_SEQ, SCALE,
        (long long)NN_SEQ * 3 * DD, (long long)NN_SEQ * 3 * DD,
        (long long)NN_SEQ * NN_SEQ);

    // 3) row softmax
    softmax_kernel<<<BB * NN_SEQ, blk>>>(scores);

    // 4) ctx = P @ V  (per batch, NN)
    sgemm_kernel<false, false><<<dim3(DD / 128, NN_SEQ / 128, BB), blk>>>(
        scores, qkv + 2 * DD /*V*/, nullptr, ctx,
        NN_SEQ, NN_SEQ, 3 * DD, DD, 1.0f,
        (long long)NN_SEQ * NN_SEQ, (long long)NN_SEQ * 3 * DD,
        (long long)NN_SEQ * DD);

    // 5) out = ctx @ w_out + b_out
    sgemm_kernel<false, true><<<dim3(DD / 128, BB * NN_SEQ / 128, 1), blk>>>(
        ctx, w_out, b_out, out,
        DD, DD, DD, DD, 1.0f, 0, 0, 0);
}

// round 3
// speedup vs baseline: 3.1027x; 3.1027x over previous
#include <cuda_runtime.h>
#include <cstdint>
#include <math.h>

#define BB 4
#define NN_SEQ 4096
#define DD 768

// Scratch (allocation-free rule: __device__ globals)
__device__ float g_qkv[(size_t)BB * NN_SEQ * (3 * DD)];
__device__ float g_scores[(size_t)BB * NN_SEQ * NN_SEQ];
__device__ float g_ctx[(size_t)BB * NN_SEQ * DD];

__device__ __forceinline__ float to_tf32(float x) {
    float r;
    asm("cvt.rna.tf32.f32 %0, %1;" : "=f"(r) : "f"(x));
    return r;
}
__device__ __forceinline__ uint32_t fbits(float x) { return __float_as_uint(x); }

// ---------------------------------------------------------------------------
// tf32 mma.sync GEMM: C = alpha * A * op(B) + bias
//   A: [M,K] row-major. BT=true: B is [N,K] row-major (op(B)=B^T).
//   BT=false: B is [K,N] row-major.
// CTA tile 256x128, BK=32, 256 threads (8 warps x 64x64 warp tile).
// Frag-order shared memory: A frag (m16k8) stride 132 floats; B frag (k8n8)
// stride 66 floats. Double buffered. All dims tile-exact.
// ---------------------------------------------------------------------------
#define SA 132
#define SBF 66
#define ABUF 8448            // 64 frags * 132
#define BBUF 4224            // 64 frags * 66
#define SMEM_FLOATS (2 * ABUF + 2 * BBUF)   // 25344 floats = 101376 B

template <bool BT, bool HAS_BIAS>
__global__ __launch_bounds__(256, 1) void tc_gemm(
    const float* __restrict__ A, const float* __restrict__ B,
    const float* __restrict__ bias, float* __restrict__ C,
    int K, int lda, int ldb, int ldc, float alpha,
    long long sA, long long sB, long long sC)
{
    extern __shared__ float sm[];   // [A0][A1][B0][B1]

    const int t = threadIdx.x;
    const int lane = t & 31, wid = t >> 5;
    const int warp_m = wid >> 1;    // 0..3 -> rows warp_m*64
    const int warp_n = wid & 1;     // 0..1 -> cols warp_n*64
    const int bx = blockIdx.x, by = blockIdx.y, bz = blockIdx.z;

    A += (size_t)bz * sA + (size_t)(by * 256) * lda;
    B += (size_t)bz * sB;
    C += (size_t)bz * sC;

    float acc[4][8][4];
#pragma unroll
    for (int i = 0; i < 4; i++)
#pragma unroll
        for (int j = 0; j < 8; j++)
#pragma unroll
            for (int r = 0; r < 4; r++) acc[i][j][r] = 0.0f;

    float4 ra[8], rb[4];
    const int ar  = t >> 3;          // A row base (+32*s)
    const int ac4 = (t & 7) * 4;     // A col within chunk

    const int nch = K / 32;

    // ---- gmem loads for chunk c into registers ----
    auto LOAD_GMEM = [&](int c) {
        const int k0 = c * 32;
#pragma unroll
        for (int s = 0; s < 8; s++)
            ra[s] = *(const float4*)(A + (size_t)(ar + 32 * s) * lda + k0 + ac4);
        if (BT) {
#pragma unroll
            for (int s = 0; s < 4; s++)
                rb[s] = *(const float4*)(B + (size_t)(bx * 128 + (t >> 3) + 32 * s) * ldb + k0 + ac4);
        } else {
#pragma unroll
            for (int s = 0; s < 4; s++)
                rb[s] = *(const float4*)(B + (size_t)(k0 + 8 * s + (t & 7)) * ldb + bx * 128 + 4 * (t >> 3));
        }
    };

    // ---- convert + scatter-store registers into frag-order smem ----
    auto STORE_SMEM = [&](int buf) {
        float* As = sm + buf * ABUF;
        float* Bs = sm + 2 * ABUF + buf * BBUF;
        const int ks = ac4 >> 3;
        const int rega2 = 2 * ((ac4 >> 2) & 1);
#pragma unroll
        for (int s = 0; s < 8; s++) {
            int r = ar + 32 * s;
            int base = ((r >> 4) * 4 + ks) * SA + (r & 7) * 16 + ((r >> 3) & 1) + rega2;
            As[base + 0]  = to_tf32(ra[s].x);
            As[base + 4]  = to_tf32(ra[s].y);
            As[base + 8]  = to_tf32(ra[s].z);
            As[base + 12] = to_tf32(ra[s].w);
        }
        if (BT) {
            const int regb = (ac4 >> 2) & 1;
#pragma unroll
            for (int s = 0; s < 4; s++) {
                int n = (t >> 3) + 32 * s;
                int base = ((n >> 3) * 4 + ks) * SBF + (n & 7) * 8 + regb;
                Bs[base + 0] = to_tf32(rb[s].x);
                Bs[base + 2] = to_tf32(rb[s].y);
                Bs[base + 4] = to_tf32(rb[s].z);
                Bs[base + 6] = to_tf32(rb[s].w);
            }
        } else {
#pragma unroll
            for (int s = 0; s < 4; s++) {
                int kr = 8 * s + (t & 7);
                int n0 = 4 * (t >> 3);
                int base = ((n0 >> 3) * 4 + s) * SBF + ((n0 & 7) * 4 + (kr & 3)) * 2 + ((kr >> 2) & 1);
                Bs[base + 0]  = to_tf32(rb[s].x);
                Bs[base + 8]  = to_tf32(rb[s].y);
                Bs[base + 16] = to_tf32(rb[s].z);
                Bs[base + 24] = to_tf32(rb[s].w);
            }
        }
    };

    // ---- frag loads + mma for one chunk ----
    auto COMPUTE = [&](int buf) {
        const float* As = sm + buf * ABUF;
        const float* Bs = sm + 2 * ABUF + buf * BBUF;
#pragma unroll
        for (int ks = 0; ks < 4; ks++) {
            uint32_t a[4][4];
            uint32_t b[8][2];
#pragma unroll
            for (int i = 0; i < 4; i++) {
                float4 v = *(const float4*)(As + ((warp_m * 4 + i) * 4 + ks) * SA + lane * 4);
                a[i][0] = fbits(v.x); a[i][1] = fbits(v.y);
                a[i][2] = fbits(v.z); a[i][3] = fbits(v.w);
            }
#pragma unroll
            for (int j = 0; j < 8; j++) {
                float2 v = *(const float2*)(Bs + ((warp_n * 8 + j) * 4 + ks) * SBF + lane * 2);
                b[j][0] = fbits(v.x); b[j][1] = fbits(v.y);
            }
#pragma unroll
            for (int i = 0; i < 4; i++)
#pragma unroll
                for (int j = 0; j < 8; j++) {
                    asm volatile(
                        "mma.sync.aligned.m16n8k8.row.col.f32.tf32.tf32.f32 "
                        "{%0,%1,%2,%3}, {%4,%5,%6,%7}, {%8,%9}, {%0,%1,%2,%3};"
                        : "+f"(acc[i][j][0]), "+f"(acc[i][j][1]),
                          "+f"(acc[i][j][2]), "+f"(acc[i][j][3])
                        : "r"(a[i][0]), "r"(a[i][1]), "r"(a[i][2]), "r"(a[i][3]),
                          "r"(b[j][0]), "r"(b[j][1]));
                }
        }
    };

    LOAD_GMEM(0);
    STORE_SMEM(0);
    __syncthreads();
    for (int c = 0; c < nch; c++) {
        if (c + 1 < nch) LOAD_GMEM(c + 1);
        COMPUTE(c & 1);
        if (c + 1 < nch) STORE_SMEM((c + 1) & 1);
        __syncthreads();
    }

    // ---- epilogue ----
    const int g  = lane >> 2;
    const int tg = lane & 3;
#pragma unroll
    for (int i = 0; i < 4; i++) {
        int row0 = by * 256 + warp_m * 64 + i * 16 + g;
#pragma unroll
        for (int j = 0; j < 8; j++) {
            int col = bx * 128 + warp_n * 64 + j * 8 + tg * 2;
            float b0 = 0.0f, b1 = 0.0f;
            if (HAS_BIAS) { b0 = bias[col]; b1 = bias[col + 1]; }
            float2 v0 = make_float2(acc[i][j][0] * alpha + b0, acc[i][j][1] * alpha + b1);
            float2 v1 = make_float2(acc[i][j][2] * alpha + b0, acc[i][j][3] * alpha + b1);
            *(float2*)(C + (size_t)row0 * ldc + col)       = v0;
            *(float2*)(C + (size_t)(row0 + 8) * ldc + col) = v1;
        }
    }
}

// ---------------------------------------------------------------------------
// Row softmax over 4096 columns. One block (256 thr) per row, float4 I/O.
// ---------------------------------------------------------------------------
__global__ __launch_bounds__(256) void softmax_kernel(float* __restrict__ scores)
{
    const int ncols4 = NN_SEQ / 4;
    float4* row = (float4*)(scores + (size_t)blockIdx.x * NN_SEQ);
    const int t = threadIdx.x;
    __shared__ float red[8];

    float m = -1e30f;
    for (int i = t; i < ncols4; i += 256) {
        float4 v = row[i];
        m = fmaxf(m, fmaxf(fmaxf(v.x, v.y), fmaxf(v.z, v.w)));
    }
#pragma unroll
    for (int o = 16; o > 0; o >>= 1) m = fmaxf(m, __shfl_xor_sync(0xffffffffu, m, o));
    if ((t & 31) == 0) red[t >> 5] = m;
    __syncthreads();
    if (t < 8) {
        float v = red[t];
#pragma unroll
        for (int o = 4; o > 0; o >>= 1) v = fmaxf(v, __shfl_xor_sync(0xffu, v, o));
        if (t == 0) red[0] = v;
    }
    __syncthreads();
    m = red[0];
    __syncthreads();

    float s = 0.0f;
    for (int i = t; i < ncols4; i += 256) {
        float4 v = row[i];
        v.x = __expf(v.x - m); v.y = __expf(v.y - m);
        v.z = __expf(v.z - m); v.w = __expf(v.w - m);
        s += v.x + v.y + v.z + v.w;
        row[i] = v;
    }
#pragma unroll
    for (int o = 16; o > 0; o >>= 1) s += __shfl_xor_sync(0xffffffffu, s, o);
    if ((t & 31) == 0) red[t >> 5] = s;
    __syncthreads();
    if (t < 8) {
        float v = red[t];
#pragma unroll
        for (int o = 4; o > 0; o >>= 1) v += __shfl_xor_sync(0xffu, v, o);
        if (t == 0) red[0] = v;
    }
    __syncthreads();
    float inv = 1.0f / red[0];

    for (int i = t; i < ncols4; i += 256) {
        float4 v = row[i];
        v.x *= inv; v.y *= inv; v.z *= inv; v.w *= inv;
        row[i] = v;
    }
}

// ---------------------------------------------------------------------------
extern "C" void kernel_launch(void* const* d_in, const int* in_sizes, int n_in,
                              void* d_out, int out_size)
{
    const float* x     = (const float*)d_in[0];   // [4,4096,768]
    const float* w_qkv = (const float*)d_in[1];   // [768,2304]
    const float* b_qkv = (const float*)d_in[2];   // [2304]
    const float* w_out = (const float*)d_in[3];   // [768,768]
    const float* b_out = (const float*)d_in[4];   // [768]
    float* out = (float*)d_out;                   // [4,4096,768]

    float *qkv, *scores, *ctx;
    cudaGetSymbolAddress((void**)&qkv,    g_qkv);
    cudaGetSymbolAddress((void**)&scores, g_scores);
    cudaGetSymbolAddress((void**)&ctx,    g_ctx);

    const float SCALE = 1.0f / sqrtf((float)DD);
    const int smem = SMEM_FLOATS * 4;   // 101376 bytes

    cudaFuncSetAttribute(tc_gemm<false, true>,
                         cudaFuncAttributeMaxDynamicSharedMemorySize, smem);
    cudaFuncSetAttribute(tc_gemm<true, false>,
                         cudaFuncAttributeMaxDynamicSharedMemorySize, smem);
    cudaFuncSetAttribute(tc_gemm<false, false>,
                         cudaFuncAttributeMaxDynamicSharedMemorySize, smem);

    dim3 blk(256);

    // 1) QKV projection: [16384,768] x [768,2304] + b  (NN)
    tc_gemm<false, true><<<dim3(3 * DD / 128, BB * NN_SEQ / 256, 1), blk, smem>>>(
        x, w_qkv, b_qkv, qkv,
        DD, DD, 3 * DD, 3 * DD, 1.0f, 0, 0, 0);

    // 2) scores = SCALE * Q @ K^T  (per batch, NT)
    tc_gemm<true, false><<<dim3(NN_SEQ / 128, NN_SEQ / 256, BB), blk, smem>>>(
        qkv, qkv + DD, nullptr, scores,
        DD, 3 * DD, 3 * DD, NN_SEQ, SCALE,
        (long long)NN_SEQ * 3 * DD, (long long)NN_SEQ * 3 * DD,
        (long long)NN_SEQ * NN_SEQ);

    // 3) row softmax
    softmax_kernel<<<BB * NN_SEQ, blk>>>(scores);

    // 4) ctx = P @ V  (per batch, NN)
    tc_gemm<false, false><<<dim3(DD / 128, NN_SEQ / 256, BB), blk, smem>>>(
        scores, qkv + 2 * DD, nullptr, ctx,
        NN_SEQ, NN_SEQ, 3 * DD, DD, 1.0f,
        (long long)NN_SEQ * NN_SEQ, (long long)NN_SEQ * 3 * DD,
        (long long)NN_SEQ * DD);

    // 5) out = ctx @ w_out + b_out  (NN)
    tc_gemm<false, true><<<dim3(DD / 128, BB * NN_SEQ / 256, 1), blk, smem>>>(
        ctx, w_out, b_out, out,
        DD, DD, DD, DD, 1.0f, 0, 0, 0);
}

// round 6
// speedup vs baseline: 4.2189x; 1.3597x over previous
#include <cuda_runtime.h>
#include <cuda_fp16.h>
#include <cstdint>
#include <math.h>

#define BB 4
#define NN_SEQ 4096
#define DD 768

// Scratch (allocation-free rule: __device__ globals)
__device__ float g_qkv[(size_t)BB * NN_SEQ * (3 * DD)];
__device__ float g_scores[(size_t)BB * NN_SEQ * NN_SEQ];
__device__ float g_ctx[(size_t)BB * NN_SEQ * DD];

__device__ __forceinline__ uint32_t h2bits(float a, float b) {
    __half2 h = __floats2half2_rn(a, b);   // a -> low half (even k)
    return *(uint32_t*)&h;
}

// ---------------------------------------------------------------------------
// fp16 mma.sync GEMM (m16n8k16, fp32 accum): C = alpha * A * op(B) + bias
//   A: [M,K] row-major. BT=true: B is [N,K] row-major (op(B)=B^T).
//   BT=false: B is [K,N] row-major.
// CTA tile 256x128, BK=32, 256 threads (8 warps x 64x64 warp tile).
// Frag-order smem (u32 units): A frag stride 132, B frag stride 66.
// Double buffered; gmem prefetch staged in registers; fp32->fp16 at smem store.
// ---------------------------------------------------------------------------
#define SA 132               // u32 per A frag (128 + 4 pad)
#define SBF 66               // u32 per B frag (64 + 2 pad)
#define ABUF 4224            // 32 frags * 132
#define BBUF 2112            // 32 frags * 66
#define SMEM_U32 (2 * ABUF + 2 * BBUF)   // 12672 u32 = 50688 B

template <bool BT, bool HAS_BIAS>
__global__ __launch_bounds__(256, 1) void tc_gemm(
    const float* __restrict__ A, const float* __restrict__ B,
    const float* __restrict__ bias, float* __restrict__ C,
    int K, int lda, int ldb, int ldc, float alpha,
    long long sA, long long sB, long long sC)
{
    extern __shared__ uint32_t sm[];   // [A0][A1][B0][B1]

    const int t = threadIdx.x;
    const int lane = t & 31, wid = t >> 5;
    const int warp_m = wid >> 1;    // 0..3 -> rows warp_m*64
    const int warp_n = wid & 1;     // 0..1 -> cols warp_n*64
    const int bx = blockIdx.x, by = blockIdx.y, bz = blockIdx.z;

    A += (size_t)bz * sA + (size_t)(by * 256) * lda;
    B += (size_t)bz * sB;
    C += (size_t)bz * sC;

    float acc[4][8][4];
#pragma unroll
    for (int i = 0; i < 4; i++)
#pragma unroll
        for (int j = 0; j < 8; j++)
#pragma unroll
            for (int r = 0; r < 4; r++) acc[i][j][r] = 0.0f;

    float4 ra[8], rb[4];
    const int ar  = t >> 3;          // A row base (+32*s)
    const int ac4 = (t & 7) * 4;     // k offset within chunk (0,4,...,28)

    const int nch = K / 32;

    // ---- gmem loads for chunk c into registers ----
    auto LOAD_GMEM = [&](int c) {
        const int k0 = c * 32;
#pragma unroll
        for (int s = 0; s < 8; s++)
            ra[s] = *(const float4*)(A + (size_t)(ar + 32 * s) * lda + k0 + ac4);
        if (BT) {
#pragma unroll
            for (int s = 0; s < 4; s++)
                rb[s] = *(const float4*)(B + (size_t)(bx * 128 + (t >> 3) + 32 * s) * ldb + k0 + ac4);
        } else {
#pragma unroll
            for (int s = 0; s < 4; s++)
                rb[s] = *(const float4*)(B + (size_t)(k0 + 8 * s + (t & 7)) * ldb + bx * 128 + 4 * (t >> 3));
        }
    };

    // fragment addressing pieces for the k dimension (ac4 fixed per thread)
    const int ksel   = (ac4 >> 4) & 1;        // which k16 step in chunk
    const int regk   = (ac4 >> 3) & 1;        // k'>>3 bit
    const int lpair0 = ((ac4 & 7) >> 1);      // lane tg for (ac4, ac4+1)
    const int lpair1 = (((ac4 + 2) & 7) >> 1);

    // ---- convert + scatter-store registers into frag-order smem ----
    auto STORE_SMEM = [&](int buf) {
        uint32_t* As = sm + buf * ABUF;
        uint32_t* Bs = sm + 2 * ABUF + buf * BBUF;
#pragma unroll
        for (int s = 0; s < 8; s++) {
            int m  = ar + 32 * s;
            int mp = m & 15;
            int fi  = (m >> 4) * 2 + ksel;
            int reg = (mp >> 3) + 2 * regk;
            int base = fi * SA + (mp & 7) * 16 + reg;
            As[base + lpair0 * 4] = h2bits(ra[s].x, ra[s].y);
            As[base + lpair1 * 4] = h2bits(ra[s].z, ra[s].w);
        }
        if (BT) {
#pragma unroll
            for (int s = 0; s < 4; s++) {
                int n  = (t >> 3) + 32 * s;
                int fi = (n >> 3) * 2 + ksel;
                int base = fi * SBF + (n & 7) * 8 + regk;
                Bs[base + lpair0 * 2] = h2bits(rb[s].x, rb[s].y);
                Bs[base + lpair1 * 2] = h2bits(rb[s].z, rb[s].w);
            }
        } else {
#pragma unroll
            for (int s = 0; s < 4; s++) {
                int kr = 8 * s + (t & 7);
                int n0 = 4 * (t >> 3);
                int fi_k = (kr >> 4) & 1;
                int reg  = (kr >> 3) & 1;
                int ltg  = (kr & 7) >> 1;
                int hoff = (kr & 1) * 2;
                const float v[4] = { rb[s].x, rb[s].y, rb[s].z, rb[s].w };
#pragma unroll
                for (int e = 0; e < 4; e++) {
                    int n = n0 + e;
                    int fi = (n >> 3) * 2 + fi_k;
                    int slot = fi * SBF + ((n & 7) * 4 + ltg) * 2 + reg;
                    *(__half*)((char*)(Bs + slot) + hoff) = __float2half_rn(v[e]);
                }
            }
        }
    };

    // ---- frag loads + mma for one chunk ----
    auto COMPUTE = [&](int buf) {
        const uint32_t* As = sm + buf * ABUF;
        const uint32_t* Bs = sm + 2 * ABUF + buf * BBUF;
#pragma unroll
        for (int ks = 0; ks < 2; ks++) {
            uint32_t a[4][4];
            uint32_t b[8][2];
#pragma unroll
            for (int i = 0; i < 4; i++) {
                uint4 v = *(const uint4*)(As + ((warp_m * 4 + i) * 2 + ks) * SA + lane * 4);
                a[i][0] = v.x; a[i][1] = v.y; a[i][2] = v.z; a[i][3] = v.w;
            }
#pragma unroll
            for (int j = 0; j < 8; j++) {
                uint2 v = *(const uint2*)(Bs + ((warp_n * 8 + j) * 2 + ks) * SBF + lane * 2);
                b[j][0] = v.x; b[j][1] = v.y;
            }
#pragma unroll
            for (int i = 0; i < 4; i++)
#pragma unroll
                for (int j = 0; j < 8; j++) {
                    asm volatile(
                        "mma.sync.aligned.m16n8k16.row.col.f32.f16.f16.f32 "
                        "{%0,%1,%2,%3}, {%4,%5,%6,%7}, {%8,%9}, {%0,%1,%2,%3};"
                        : "+f"(acc[i][j][0]), "+f"(acc[i][j][1]),
                          "+f"(acc[i][j][2]), "+f"(acc[i][j][3])
                        : "r"(a[i][0]), "r"(a[i][1]), "r"(a[i][2]), "r"(a[i][3]),
                          "r"(b[j][0]), "r"(b[j][1]));
                }
        }
    };

    LOAD_GMEM(0);
    STORE_SMEM(0);
    __syncthreads();
    for (int c = 0; c < nch; c++) {
        if (c + 1 < nch) LOAD_GMEM(c + 1);
        COMPUTE(c & 1);
        if (c + 1 < nch) STORE_SMEM((c + 1) & 1);
        __syncthreads();
    }

    // ---- epilogue ----
    const int g  = lane >> 2;
    const int tg = lane & 3;
#pragma unroll
    for (int i = 0; i < 4; i++) {
        int row0 = by * 256 + warp_m * 64 + i * 16 + g;
#pragma unroll
        for (int j = 0; j < 8; j++) {
            int col = bx * 128 + warp_n * 64 + j * 8 + tg * 2;
            float b0 = 0.0f, b1 = 0.0f;
            if (HAS_BIAS) { b0 = bias[col]; b1 = bias[col + 1]; }
            float2 v0 = make_float2(acc[i][j][0] * alpha + b0, acc[i][j][1] * alpha + b1);
            float2 v1 = make_float2(acc[i][j][2] * alpha + b0, acc[i][j][3] * alpha + b1);
            *(float2*)(C + (size_t)row0 * ldc + col)       = v0;
            *(float2*)(C + (size_t)(row0 + 8) * ldc + col) = v1;
        }
    }
}

// ---------------------------------------------------------------------------
// Row softmax over 4096 columns. One block (256 thr) per row, float4 I/O.
// ---------------------------------------------------------------------------
__global__ __launch_bounds__(256) void softmax_kernel(float* __restrict__ scores)
{
    const int ncols4 = NN_SEQ / 4;
    float4* row = (float4*)(scores + (size_t)blockIdx.x * NN_SEQ);
    const int t = threadIdx.x;
    __shared__ float red[8];

    float m = -1e30f;
    for (int i = t; i < ncols4; i += 256) {
        float4 v = row[i];
        m = fmaxf(m, fmaxf(fmaxf(v.x, v.y), fmaxf(v.z, v.w)));
    }
#pragma unroll
    for (int o = 16; o > 0; o >>= 1) m = fmaxf(m, __shfl_xor_sync(0xffffffffu, m, o));
    if ((t & 31) == 0) red[t >> 5] = m;
    __syncthreads();
    if (t < 8) {
        float v = red[t];
#pragma unroll
        for (int o = 4; o > 0; o >>= 1) v = fmaxf(v, __shfl_xor_sync(0xffu, v, o));
        if (t == 0) red[0] = v;
    }
    __syncthreads();
    m = red[0];
    __syncthreads();

    float s = 0.0f;
    for (int i = t; i < ncols4; i += 256) {
        float4 v = row[i];
        v.x = __expf(v.x - m); v.y = __expf(v.y - m);
        v.z = __expf(v.z - m); v.w = __expf(v.w - m);
        s += v.x + v.y + v.z + v.w;
        row[i] = v;
    }
#pragma unroll
    for (int o = 16; o > 0; o >>= 1) s += __shfl_xor_sync(0xffffffffu, s, o);
    if ((t & 31) == 0) red[t >> 5] = s;
    __syncthreads();
    if (t < 8) {
        float v = red[t];
#pragma unroll
        for (int o = 4; o > 0; o >>= 1) v += __shfl_xor_sync(0xffu, v, o);
        if (t == 0) red[0] = v;
    }
    __syncthreads();
    float inv = 1.0f / red[0];

    for (int i = t; i < ncols4; i += 256) {
        float4 v = row[i];
        v.x *= inv; v.y *= inv; v.z *= inv; v.w *= inv;
        row[i] = v;
    }
}

// ---------------------------------------------------------------------------
extern "C" void kernel_launch(void* const* d_in, const int* in_sizes, int n_in,
                              void* d_out, int out_size)
{
    const float* x     = (const float*)d_in[0];   // [4,4096,768]
    const float* w_qkv = (const float*)d_in[1];   // [768,2304]
    const float* b_qkv = (const float*)d_in[2];   // [2304]
    const float* w_out = (const float*)d_in[3];   // [768,768]
    const float* b_out = (const float*)d_in[4];   // [768]
    float* out = (float*)d_out;                   // [4,4096,768]

    float *qkv, *scores, *ctx;
    cudaGetSymbolAddress((void**)&qkv,    g_qkv);
    cudaGetSymbolAddress((void**)&scores, g_scores);
    cudaGetSymbolAddress((void**)&ctx,    g_ctx);

    const float SCALE = 1.0f / sqrtf((float)DD);
    const int smem = SMEM_U32 * 4;   // 50688 bytes

    cudaFuncSetAttribute(tc_gemm<false, true>,
                         cudaFuncAttributeMaxDynamicSharedMemorySize, smem);
    cudaFuncSetAttribute(tc_gemm<true, false>,
                         cudaFuncAttributeMaxDynamicSharedMemorySize, smem);
    cudaFuncSetAttribute(tc_gemm<false, false>,
                         cudaFuncAttributeMaxDynamicSharedMemorySize, smem);

    dim3 blk(256);

    // 1) QKV projection: [16384,768] x [768,2304] + b  (NN)
    tc_gemm<false, true><<<dim3(3 * DD / 128, BB * NN_SEQ / 256, 1), blk, smem>>>(
        x, w_qkv, b_qkv, qkv,
        DD, DD, 3 * DD, 3 * DD, 1.0f, 0, 0, 0);

    // 2) scores = SCALE * Q @ K^T  (per batch, NT)
    tc_gemm<true, false><<<dim3(NN_SEQ / 128, NN_SEQ / 256, BB), blk, smem>>>(
        qkv, qkv + DD, nullptr, scores,
        DD, 3 * DD, 3 * DD, NN_SEQ, SCALE,
        (long long)NN_SEQ * 3 * DD, (long long)NN_SEQ * 3 * DD,
        (long long)NN_SEQ * NN_SEQ);

    // 3) row softmax
    softmax_kernel<<<BB * NN_SEQ, blk>>>(scores);

    // 4) ctx = P @ V  (per batch, NN)
    tc_gemm<false, false><<<dim3(DD / 128, NN_SEQ / 256, BB), blk, smem>>>(
        scores, qkv + 2 * DD, nullptr, ctx,
        NN_SEQ, NN_SEQ, 3 * DD, DD, 1.0f,
        (long long)NN_SEQ * NN_SEQ, (long long)NN_SEQ * 3 * DD,
        (long long)NN_SEQ * DD);

    // 5) out = ctx @ w_out + b_out  (NN)
    tc_gemm<false, true><<<dim3(DD / 128, BB * NN_SEQ / 256, 1), blk, smem>>>(
        ctx, w_out, b_out, out,
        DD, DD, DD, DD, 1.0f, 0, 0, 0);
}